// round 10
// baseline (speedup 1.0000x reference)
#include <cuda_runtime.h>

#define NFRAME 320
#define HOP    160
#define LAG    33
#define NTAU_OUT 224          // 257 - 33
#define FN     1000
#define SLEN   160000
#define EXT_LEN 576           // N + TAU - 1
#define EPS    1e-5f

#define WARPS_PER_BLK 4

typedef unsigned long long u64;

__device__ __forceinline__ u64 pk(float a, float b) {
    u64 r; asm("mov.b64 %0, {%1, %2};" : "=l"(r) : "f"(a), "f"(b)); return r;
}
__device__ __forceinline__ void fma2(u64& d, u64 a, u64 b) {
    asm("fma.rn.f32x2 %0, %1, %2, %0;" : "+l"(d) : "l"(a), "l"(b));
}
__device__ __forceinline__ float hadd2(u64 v) {
    float lo, hi;
    asm("mov.b64 {%0, %1}, %2;" : "=f"(lo), "=f"(hi) : "l"(v));
    return lo + hi;
}

// One WARP per (b, f). Lane computes 7 lags tau = 33 + 7*lane + k.
// Dot products accumulated pairwise over n with fma.rn.f32x2.
__global__ __launch_bounds__(32 * WARPS_PER_BLK)
void xcorr_kernel(const float* __restrict__ x, float* __restrict__ out)
{
    const int w    = threadIdx.x >> 5;
    const int lane = threadIdx.x & 31;
    const int bf   = blockIdx.x * WARPS_PER_BLK + w;
    const int b    = bf / FN;
    const int f    = bf % FN;
    const float* __restrict__ xb = x + (size_t)b * SLEN;

    __shared__ __align__(16) float sExt[WARPS_PER_BLK][EXT_LEN + 8]; // +8: pad for tail window loads
    __shared__ float sCs[WARPS_PER_BLK][EXT_LEN + 1];

    float* ext = sExt[w];
    float* cs  = sCs[w];

    // ---- Load ext[576]: frame f (320) ++ first 256 of frame f+1 (wrap @ f=999) ----
    #pragma unroll
    for (int r = 0; r < 18; r++) {
        int j = lane + 32 * r;
        int idx;
        if (j < NFRAME)        idx = HOP * f + j;
        else if (f == FN - 1)  idx = j - NFRAME;           // wrap to frame 0
        else                   idx = HOP * f + j - HOP;    // frame f+1
        ext[j] = (idx < SLEN) ? xb[idx] : 0.0f;            // zero-pad tail
    }
    if (lane < 8) ext[EXT_LEN + lane] = 0.0f;              // pad
    __syncwarp();

    // ---- Prefix sum of squares (per-warp): lane owns ext[18L .. 18L+17] ----
    {
        float loc[18];
        float s = 0.0f;
        #pragma unroll
        for (int i = 0; i < 18; i++) {
            float v = ext[18 * lane + i];
            s += v * v;
            loc[i] = s;
        }
        float v = s;
        #pragma unroll
        for (int d = 1; d < 32; d <<= 1) {
            float n = __shfl_up_sync(0xffffffffu, v, d);
            if (lane >= d) v += n;
        }
        float excl = v - s;
        if (lane == 0) cs[0] = 0.0f;
        #pragma unroll
        for (int i = 0; i < 18; i++)
            cs[18 * lane + 1 + i] = excl + loc[i];
    }
    __syncwarp();

    // ---- Main loop ----
    const int tau0 = LAG + 7 * lane;
    const float* __restrict__ wp = ext + tau0;   // window source (stride-7 lanes: conflict-free)

    // initial window w[0..7] as 4 aligned f32x2 pairs
    float iw0 = wp[0], iw1 = wp[1], iw2 = wp[2], iw3 = wp[3];
    float iw4 = wp[4], iw5 = wp[5], iw6 = wp[6], iw7 = wp[7];
    u64 d0 = pk(iw0, iw1), d1 = pk(iw2, iw3), d2 = pk(iw4, iw5), d3 = pk(iw6, iw7);
    const float c1 = iw1, c3 = iw3, c5 = iw5;    // odd-k n=0 window values
    const float f0 = ext[0];                     // fr[0]

    u64 a0 = 0, a1 = 0, a2 = 0, a3 = 0, a4 = 0, a5 = 0, a6 = 0;

    const float4* __restrict__ frv = (const float4*)ext;   // frame = ext[0:320]

    #pragma unroll 2
    for (int g = 0; g < NFRAME / 8; g++) {       // 8 samples per group
        const int n = 8 * g;
        float4 fa = frv[2 * g];                  // fr[n .. n+3]   (broadcast)
        float4 fb = frv[2 * g + 1];              // fr[n+4 .. n+7] (broadcast)
        float nxv = ext[n + 8];                  // fr[n+8] (valid: <=320)
        float nx  = (g < NFRAME / 8 - 1) ? nxv : 0.0f;   // fr[320] := 0

        // ---- pair 0: samples (n, n+1) ----
        {
            u64 mab = pk(fa.x, fa.y), mbc = pk(fa.y, fa.z);
            fma2(a0, mab, d0); fma2(a2, mab, d1); fma2(a4, mab, d2); fma2(a6, mab, d3);
            fma2(a1, mbc, d1); fma2(a3, mbc, d2); fma2(a5, mbc, d3);
        }
        u64 d4 = pk(wp[n + 8], wp[n + 9]);
        // ---- pair 1: samples (n+2, n+3) ----
        {
            u64 mab = pk(fa.z, fa.w), mbc = pk(fa.w, fb.x);
            fma2(a0, mab, d1); fma2(a2, mab, d2); fma2(a4, mab, d3); fma2(a6, mab, d4);
            fma2(a1, mbc, d2); fma2(a3, mbc, d3); fma2(a5, mbc, d4);
        }
        u64 d5 = pk(wp[n + 10], wp[n + 11]);
        // ---- pair 2: samples (n+4, n+5) ----
        {
            u64 mab = pk(fb.x, fb.y), mbc = pk(fb.y, fb.z);
            fma2(a0, mab, d2); fma2(a2, mab, d3); fma2(a4, mab, d4); fma2(a6, mab, d5);
            fma2(a1, mbc, d3); fma2(a3, mbc, d4); fma2(a5, mbc, d5);
        }
        u64 d6 = pk(wp[n + 12], wp[n + 13]);
        // ---- pair 3: samples (n+6, n+7) ----
        {
            u64 mab = pk(fb.z, fb.w), mbc = pk(fb.w, nx);
            fma2(a0, mab, d3); fma2(a2, mab, d4); fma2(a4, mab, d5); fma2(a6, mab, d6);
            fma2(a1, mbc, d4); fma2(a3, mbc, d5); fma2(a5, mbc, d6);
        }
        u64 d7 = pk(wp[n + 14], wp[n + 15]);

        d0 = d4; d1 = d5; d2 = d6; d3 = d7;
    }

    // ---- Horizontal add + odd-k n=0 correction ----
    float r0 = hadd2(a0);
    float r1 = hadd2(a1) + f0 * c1;
    float r2 = hadd2(a2);
    float r3 = hadd2(a3) + f0 * c3;
    float r4 = hadd2(a4);
    float r5 = hadd2(a5) + f0 * c5;
    float r6 = hadd2(a6);

    // ---- Normalize and store ----
    const float e0 = cs[NFRAME];
    float* __restrict__ o = out + (size_t)bf * NTAU_OUT + 7 * lane;
    float acc[7] = {r0, r1, r2, r3, r4, r5, r6};
    #pragma unroll
    for (int k = 0; k < 7; k++) {
        float etau = cs[tau0 + k + NFRAME] - cs[tau0 + k];
        o[k] = 2.0f * acc[k] / (e0 + etau + EPS);
    }
}

extern "C" void kernel_launch(void* const* d_in, const int* in_sizes, int n_in,
                              void* d_out, int out_size)
{
    const float* x = (const float*)d_in[0];
    float* out = (float*)d_out;
    (void)in_sizes; (void)n_in; (void)out_size;
    xcorr_kernel<<<32 * FN / WARPS_PER_BLK, 32 * WARPS_PER_BLK>>>(x, out);
}

// round 14
// speedup vs baseline: 1.0797x; 1.0797x over previous
#include <cuda_runtime.h>

#define NFRAME 320
#define HOP    160
#define LAG    33
#define NTAU_OUT 224          // 257 - 33
#define FN     1000
#define SLEN   160000
#define EXT_LEN 576           // N + TAU - 1
#define EPS    1e-5f

#define WARPS_PER_BLK 4

typedef unsigned long long u64;

__device__ __forceinline__ u64 pk(float a, float b) {
    u64 r; asm("mov.b64 %0, {%1, %2};" : "=l"(r) : "f"(a), "f"(b)); return r;
}
__device__ __forceinline__ void fma2(u64& d, u64 a, u64 b) {
    asm("fma.rn.f32x2 %0, %1, %2, %0;" : "+l"(d) : "l"(a), "l"(b));
}
__device__ __forceinline__ float hadd2(u64 v) {
    float lo, hi;
    asm("mov.b64 {%0, %1}, %2;" : "=f"(lo), "=f"(hi) : "l"(v));
    return lo + hi;
}

// One WARP per (b, f). Lane computes 7 lags tau = 33 + 7*lane + k.
// f32x2 pairwise accumulation; ALL 64-bit operands come from aligned LDS.64
// (dual shifted copies E0/E1 of ext) — no mov.b64 packing in the hot loop.
// NOTE: per-warp rows of E0/E1 MUST be a multiple of 8 bytes -> even float counts.
__global__ __launch_bounds__(32 * WARPS_PER_BLK)
void xcorr_kernel(const float* __restrict__ x, float* __restrict__ out)
{
    const int w    = threadIdx.x >> 5;
    const int lane = threadIdx.x & 31;
    const int bf   = blockIdx.x * WARPS_PER_BLK + w;
    const int b    = bf / FN;
    const int f    = bf % FN;
    const float* __restrict__ xb = x + (size_t)b * SLEN;

    __shared__ __align__(16) float sE0[WARPS_PER_BLK][EXT_LEN + 8];   // 584 floats/row (8B-div)
    __shared__ __align__(16) float sE1[WARPS_PER_BLK][EXT_LEN + 10];  // 586 floats/row (8B-div)
    __shared__ float sCs[WARPS_PER_BLK][EXT_LEN + 1];

    float* E0 = sE0[w];
    float* E1 = sE1[w];   // E1[j] = ext[j+1]
    float* cs = sCs[w];

    // ---- Load ext[576]: frame f (320) ++ first 256 of frame f+1 (wrap @ f=999) ----
    #pragma unroll
    for (int r = 0; r < 18; r++) {
        int j = lane + 32 * r;
        int idx;
        if (j < NFRAME)        idx = HOP * f + j;
        else if (f == FN - 1)  idx = j - NFRAME;           // wrap to frame 0
        else                   idx = HOP * f + j - HOP;    // frame f+1
        float v = (idx < SLEN) ? xb[idx] : 0.0f;           // zero-pad tail
        E0[j] = v;
        if (j > 0) E1[j - 1] = v;                          // shifted copy
    }
    if (lane < 8)  E0[EXT_LEN + lane] = 0.0f;              // E0[576..583] = 0
    if (lane < 11) E1[EXT_LEN - 1 + lane] = 0.0f;          // E1[575..585] = 0
    __syncwarp();

    // ---- Prefix sum of squares (per-warp): lane owns ext[18L .. 18L+17] ----
    {
        float loc[18];
        float s = 0.0f;
        #pragma unroll
        for (int i = 0; i < 18; i++) {
            float v = E0[18 * lane + i];
            s += v * v;
            loc[i] = s;
        }
        float v = s;
        #pragma unroll
        for (int d = 1; d < 32; d <<= 1) {
            float n = __shfl_up_sync(0xffffffffu, v, d);
            if (lane >= d) v += n;
        }
        float excl = v - s;
        if (lane == 0) cs[0] = 0.0f;
        #pragma unroll
        for (int i = 0; i < 18; i++)
            cs[18 * lane + 1 + i] = excl + loc[i];
    }
    __syncwarp();

    // ---- Main loop ----
    const int tau0 = LAG + 7 * lane;
    // wpair[i] = (ext[tau0+2i], ext[tau0+2i+1]), always 8B-aligned
    const u64* wpair = (tau0 & 1) ? (const u64*)(E1 + (tau0 - 1))
                                  : (const u64*)(E0 + tau0);
    const u64* m0 = (const u64*)E0;   // m0[i] = (ext[2i],   ext[2i+1])  broadcast
    const u64* m1 = (const u64*)E1;   // m1[i] = (ext[2i+1], ext[2i+2])  broadcast

    u64 d0 = wpair[0], d1 = wpair[1], d2 = wpair[2], d3 = wpair[3];
    const float c1 = E0[tau0 + 1], c3 = E0[tau0 + 3], c5 = E0[tau0 + 5];
    const float f0 = E0[0];

    u64 a0 = 0, a1 = 0, a2 = 0, a3 = 0, a4 = 0, a5 = 0, a6 = 0;

    #pragma unroll 3
    for (int g = 0; g < NFRAME / 8 - 1; g++) {   // groups 0..38 (8 samples each)
        const int h = 4 * g;

        // samples (8g, 8g+1)
        {
            u64 mab = m0[h + 0], mbc = m1[h + 0];
            fma2(a0, mab, d0); fma2(a2, mab, d1); fma2(a4, mab, d2); fma2(a6, mab, d3);
            fma2(a1, mbc, d1); fma2(a3, mbc, d2); fma2(a5, mbc, d3);
        }
        u64 d4 = wpair[h + 4];
        // samples (8g+2, 8g+3)
        {
            u64 mab = m0[h + 1], mbc = m1[h + 1];
            fma2(a0, mab, d1); fma2(a2, mab, d2); fma2(a4, mab, d3); fma2(a6, mab, d4);
            fma2(a1, mbc, d2); fma2(a3, mbc, d3); fma2(a5, mbc, d4);
        }
        u64 d5 = wpair[h + 5];
        // samples (8g+4, 8g+5)
        {
            u64 mab = m0[h + 2], mbc = m1[h + 2];
            fma2(a0, mab, d2); fma2(a2, mab, d3); fma2(a4, mab, d4); fma2(a6, mab, d5);
            fma2(a1, mbc, d3); fma2(a3, mbc, d4); fma2(a5, mbc, d5);
        }
        u64 d6 = wpair[h + 6];
        // samples (8g+6, 8g+7)
        {
            u64 mab = m0[h + 3], mbc = m1[h + 3];
            fma2(a0, mab, d3); fma2(a2, mab, d4); fma2(a4, mab, d5); fma2(a6, mab, d6);
            fma2(a1, mbc, d4); fma2(a3, mbc, d5); fma2(a5, mbc, d6);
        }
        u64 d7 = wpair[h + 7];

        d0 = d4; d1 = d5; d2 = d6; d3 = d7;
    }

    // ---- Peeled final group (g = 39, samples 312..319): fr[320] := 0 ----
    {
        const int h = 4 * 39;   // 156
        {
            u64 mab = m0[h + 0], mbc = m1[h + 0];
            fma2(a0, mab, d0); fma2(a2, mab, d1); fma2(a4, mab, d2); fma2(a6, mab, d3);
            fma2(a1, mbc, d1); fma2(a3, mbc, d2); fma2(a5, mbc, d3);
        }
        u64 d4 = wpair[h + 4];
        {
            u64 mab = m0[h + 1], mbc = m1[h + 1];
            fma2(a0, mab, d1); fma2(a2, mab, d2); fma2(a4, mab, d3); fma2(a6, mab, d4);
            fma2(a1, mbc, d2); fma2(a3, mbc, d3); fma2(a5, mbc, d4);
        }
        u64 d5 = wpair[h + 5];
        {
            u64 mab = m0[h + 2], mbc = m1[h + 2];
            fma2(a0, mab, d2); fma2(a2, mab, d3); fma2(a4, mab, d4); fma2(a6, mab, d5);
            fma2(a1, mbc, d3); fma2(a3, mbc, d4); fma2(a5, mbc, d5);
        }
        u64 d6 = wpair[h + 6];
        {
            u64 mab = m0[h + 3];
            u64 mbc = pk(E0[319], 0.0f);   // (fr[319], fr[320]=0) — one pack total
            fma2(a0, mab, d3); fma2(a2, mab, d4); fma2(a4, mab, d5); fma2(a6, mab, d6);
            fma2(a1, mbc, d4); fma2(a3, mbc, d5); fma2(a5, mbc, d6);
        }
    }

    // ---- Horizontal add + odd-k n=0 correction ----
    float r0 = hadd2(a0);
    float r1 = hadd2(a1) + f0 * c1;
    float r2 = hadd2(a2);
    float r3 = hadd2(a3) + f0 * c3;
    float r4 = hadd2(a4);
    float r5 = hadd2(a5) + f0 * c5;
    float r6 = hadd2(a6);

    // ---- Normalize and store ----
    const float e0 = cs[NFRAME];
    float* __restrict__ o = out + (size_t)bf * NTAU_OUT + 7 * lane;
    float acc[7] = {r0, r1, r2, r3, r4, r5, r6};
    #pragma unroll
    for (int k = 0; k < 7; k++) {
        float etau = cs[tau0 + k + NFRAME] - cs[tau0 + k];
        o[k] = 2.0f * acc[k] / (e0 + etau + EPS);
    }
}

extern "C" void kernel_launch(void* const* d_in, const int* in_sizes, int n_in,
                              void* d_out, int out_size)
{
    const float* x = (const float*)d_in[0];
    float* out = (float*)d_out;
    (void)in_sizes; (void)n_in; (void)out_size;
    xcorr_kernel<<<32 * FN / WARPS_PER_BLK, 32 * WARPS_PER_BLK>>>(x, out);
}